// round 9
// baseline (speedup 1.0000x reference)
#include <cuda_runtime.h>
#include <cuda_bf16.h>
#include <math.h>

#define NN 50000
#define EE 800000
#define GG 64
#define DD 128
#define BN_EPS 1e-5f
#define NB_SCAN 196   // ceil(50000/256)

#define AS_PAD 36
#define BS_PAD 132
#define GEMM_SMEM ((128 * AS_PAD * 2 + 32 * BS_PAD * 2) * 4)   // 70656 B

// ---------------- scratch (device globals; no allocation) ----------------
__device__ __align__(16) float g_h[NN * DD];
__device__ __align__(16) float g_act[NN * DD];
__device__ __align__(16) int2  g_csr[EE];          // {src, coef bits} packed
__device__ __align__(16) int   g_rowptr[NN + 1];
__device__ __align__(16) int   g_counts[NN];
__device__ __align__(16) int   g_cursor[NN];
__device__ __align__(16) float g_dinv[NN];
__device__ __align__(16) float g_selfw[NN];
__device__ __align__(16) int   g_bsum[NB_SCAN];
__device__ __align__(16) int   g_boff[NB_SCAN];
__device__ __align__(16) float g_Wp[DD * DD];
__device__ __align__(16) float g_cvec[DD];
__device__ __align__(16) float g_bias2[DD];
__device__ __align__(16) float g_colsum[DD];
__device__ __align__(16) float g_colsumsq[DD];
__device__ __align__(16) float g_scale[DD];
__device__ __align__(16) float g_shift[DD];

// ---------------- tf32 helpers ----------------
__device__ __forceinline__ unsigned f2tf32(float x) {
    unsigned r;
    asm("cvt.rna.tf32.f32 %0, %1;" : "=r"(r) : "f"(x));
    return r;
}
__device__ __forceinline__ void mma_tf32(float* d, const unsigned* a, unsigned b0, unsigned b1) {
    asm volatile(
        "mma.sync.aligned.m16n8k8.row.col.f32.tf32.tf32.f32 "
        "{%0,%1,%2,%3}, {%4,%5,%6,%7}, {%8,%9}, {%0,%1,%2,%3};"
        : "+f"(d[0]), "+f"(d[1]), "+f"(d[2]), "+f"(d[3])
        : "r"(a[0]), "r"(a[1]), "r"(a[2]), "r"(a[3]), "r"(b0), "r"(b1));
}
__device__ __forceinline__ void split_store(float v, unsigned* hp, unsigned* lp) {
    unsigned hi = f2tf32(v);
    float hif = __uint_as_float(hi);
    *hp = hi;
    *lp = f2tf32(v - hif);
}

// ---------------- init ----------------
__global__ void init_kernel(float* out) {
    int i = blockIdx.x * blockDim.x + threadIdx.x;
    if (i < NN) g_counts[i] = 0;
    if (i < DD) {
        g_scale[i] = 1.0f; g_shift[i] = 0.0f;
        g_cvec[i] = 0.0f; g_colsum[i] = 0.0f; g_colsumsq[i] = 0.0f;
    }
    if (i < GG * DD) out[i] = 0.0f;
}

// ---------------- degree count (in-degree of dst) ----------------
__global__ void count_kernel(const int* __restrict__ ei) {
    int e = blockIdx.x * blockDim.x + threadIdx.x;
    if (e >= EE) return;
    atomicAdd(&g_counts[ei[EE + e]], 1);
}

// ---------------- scan phase A (fused with deg: dinv/selfw) ----------------
__device__ __forceinline__ int block_incl_scan_256(int v, int* ws) {
    int lane = threadIdx.x & 31, wid = threadIdx.x >> 5;
    int x = v;
    #pragma unroll
    for (int off = 1; off < 32; off <<= 1) {
        int t = __shfl_up_sync(0xFFFFFFFFu, x, off);
        if (lane >= off) x += t;
    }
    if (lane == 31) ws[wid] = x;
    __syncthreads();
    if (threadIdx.x < 8) {
        int y = ws[threadIdx.x];
        #pragma unroll
        for (int off = 1; off < 8; off <<= 1) {
            int t = __shfl_up_sync(0xFFu, y, off);
            if ((int)threadIdx.x >= off) y += t;
        }
        ws[threadIdx.x] = y;
    }
    __syncthreads();
    return x + ((wid > 0) ? ws[wid - 1] : 0);
}

__global__ void scanA_kernel() {
    __shared__ int ws[8];
    int i = blockIdx.x * 256 + threadIdx.x;
    int v = (i < NN) ? g_counts[i] : 0;
    if (i < NN) {
        float deg = 1.0f + (float)v;
        g_dinv[i] = rsqrtf(deg);
        g_selfw[i] = 1.0f / deg;
    }
    int incl = block_incl_scan_256(v, ws);
    if (i < NN) {
        g_rowptr[i + 1] = incl;
        g_cursor[i] = incl - v;
    }
    if (threadIdx.x == 255) g_bsum[blockIdx.x] = incl;
}

__global__ void scanB_kernel() {
    __shared__ int ws[8];
    int b = threadIdx.x;
    int v = (b < NB_SCAN) ? g_bsum[b] : 0;
    int incl = block_incl_scan_256(v, ws);
    if (b < NB_SCAN) g_boff[b] = incl - v;
    if (b == 0) g_rowptr[0] = 0;
}

__global__ void scanC_kernel() {
    int i = blockIdx.x * 256 + threadIdx.x;
    if (i >= NN) return;
    int off = g_boff[blockIdx.x];
    g_rowptr[i + 1] += off;
    g_cursor[i] += off;
}

// ---------------- CSR fill (packed records) ----------------
__global__ void fill_kernel(const int* __restrict__ ei) {
    int e = blockIdx.x * blockDim.x + threadIdx.x;
    if (e >= EE) return;
    int s = ei[e];
    int d = ei[EE + e];
    float c = g_dinv[s] * g_dinv[d];
    int slot = atomicAdd(&g_cursor[d], 1);
    g_csr[slot] = make_int2(s, __float_as_int(c));
}

// ---------------- fold ----------------
__global__ void fold_kernel(const float* __restrict__ W, const float* __restrict__ b) {
    int idx = blockIdx.x * blockDim.x + threadIdx.x;   // 0..16383
    int k = idx >> 7;
    int n = idx & 127;
    float w = W[idx];
    g_Wp[idx] = g_scale[k] * w;
    float contrib = g_shift[k] * w;
    if (contrib != 0.0f) atomicAdd(&g_cvec[n], contrib);
    if (idx < DD) g_bias2[idx] = b[idx];
}

// ---------------- GEMM: g_h = X @ g_Wp + cvec  (tf32 mma, 2-term split) ----------------
__global__ void __launch_bounds__(256, 2) gemm_kernel(const float* __restrict__ X) {
    extern __shared__ unsigned smem[];
    unsigned* AsH = smem;
    unsigned* AsL = AsH + 128 * AS_PAD;
    unsigned* BsH = AsL + 128 * AS_PAD;
    unsigned* BsL = BsH + 32 * BS_PAD;

    int tid = threadIdx.x;
    int lane = tid & 31, warp = tid >> 5;
    int wm = warp >> 1, wn = warp & 1;
    int g = lane >> 2, tig = lane & 3;
    int m0 = blockIdx.x * 128;

    float c[2][8][4];
    #pragma unroll
    for (int mt = 0; mt < 2; mt++)
        #pragma unroll
        for (int nt = 0; nt < 8; nt++)
            #pragma unroll
            for (int q = 0; q < 4; q++) c[mt][nt][q] = 0.0f;

    int lm  = tid >> 1;
    int lk0 = (tid & 1) * 16;
    int lkb = tid >> 3;
    int ln0 = (tid & 7) * 16;
    bool valid = (m0 + lm) < NN;

    for (int chunk = 0; chunk < 4; chunk++) {
        int kk = chunk * 32;
        const float* xr = X + (size_t)(m0 + lm) * DD + kk + lk0;
        #pragma unroll
        for (int j = 0; j < 16; j += 4) {
            float4 v = valid ? *(const float4*)(xr + j) : make_float4(0.f, 0.f, 0.f, 0.f);
            int base = lm * AS_PAD + lk0 + j;
            split_store(v.x, &AsH[base + 0], &AsL[base + 0]);
            split_store(v.y, &AsH[base + 1], &AsL[base + 1]);
            split_store(v.z, &AsH[base + 2], &AsL[base + 2]);
            split_store(v.w, &AsH[base + 3], &AsL[base + 3]);
        }
        const float* wr = g_Wp + (size_t)(kk + lkb) * DD + ln0;
        #pragma unroll
        for (int j = 0; j < 16; j += 4) {
            float4 v = *(const float4*)(wr + j);
            int base = lkb * BS_PAD + ln0 + j;
            split_store(v.x, &BsH[base + 0], &BsL[base + 0]);
            split_store(v.y, &BsH[base + 1], &BsL[base + 1]);
            split_store(v.z, &BsH[base + 2], &BsL[base + 2]);
            split_store(v.w, &BsH[base + 3], &BsL[base + 3]);
        }
        __syncthreads();

        #pragma unroll
        for (int ks = 0; ks < 4; ks++) {
            int kb = ks * 8;
            unsigned aH[2][4], aL[2][4];
            #pragma unroll
            for (int mt = 0; mt < 2; mt++) {
                int r0 = (wm * 32 + mt * 16 + g) * AS_PAD;
                int r8 = r0 + 8 * AS_PAD;
                aH[mt][0] = AsH[r0 + kb + tig];
                aH[mt][1] = AsH[r8 + kb + tig];
                aH[mt][2] = AsH[r0 + kb + tig + 4];
                aH[mt][3] = AsH[r8 + kb + tig + 4];
                aL[mt][0] = AsL[r0 + kb + tig];
                aL[mt][1] = AsL[r8 + kb + tig];
                aL[mt][2] = AsL[r0 + kb + tig + 4];
                aL[mt][3] = AsL[r8 + kb + tig + 4];
            }
            #pragma unroll
            for (int nt = 0; nt < 8; nt++) {
                int ncol = wn * 64 + nt * 8 + g;
                int kr = (kb + tig) * BS_PAD + ncol;
                unsigned bH0 = BsH[kr];
                unsigned bH1 = BsH[kr + 4 * BS_PAD];
                unsigned bL0 = BsL[kr];
                unsigned bL1 = BsL[kr + 4 * BS_PAD];
                #pragma unroll
                for (int mt = 0; mt < 2; mt++) {
                    mma_tf32(c[mt][nt], aH[mt], bH0, bH1);
                    mma_tf32(c[mt][nt], aH[mt], bL0, bL1);
                    mma_tf32(c[mt][nt], aL[mt], bH0, bH1);
                }
            }
        }
        __syncthreads();
    }

    #pragma unroll
    for (int mt = 0; mt < 2; mt++) {
        int r0 = m0 + wm * 32 + mt * 16 + g;
        int r1 = r0 + 8;
        #pragma unroll
        for (int nt = 0; nt < 8; nt++) {
            int col = wn * 64 + nt * 8 + tig * 2;
            float2 cv = *(const float2*)(g_cvec + col);
            if (r0 < NN) {
                float2 o = make_float2(c[mt][nt][0] + cv.x, c[mt][nt][1] + cv.y);
                *(float2*)(g_h + (size_t)r0 * DD + col) = o;
            }
            if (r1 < NN) {
                float2 o = make_float2(c[mt][nt][2] + cv.x, c[mt][nt][3] + cv.y);
                *(float2*)(g_h + (size_t)r1 * DD + col) = o;
            }
        }
    }
}

// ---------------- aggregate + bias + relu + BN-stat accumulation ----------------
__global__ void agg_kernel() {
    int gtid = blockIdx.x * blockDim.x + threadIdx.x;
    int warp = gtid >> 5;
    int lane = threadIdx.x & 31;
    int nwarps = (gridDim.x * blockDim.x) >> 5;

    float4 bb = *(const float4*)(g_bias2 + lane * 4);
    float s0 = 0.f, s1 = 0.f, s2 = 0.f, s3 = 0.f;
    float q0 = 0.f, q1 = 0.f, q2 = 0.f, q3 = 0.f;

    for (int v = warp; v < NN; v += nwarps) {
        const float4* hv = (const float4*)(g_h + (size_t)v * DD) + lane;
        float4 h = *hv;
        float sw = g_selfw[v];
        float4 a0 = make_float4(h.x * sw, h.y * sw, h.z * sw, h.w * sw);
        float4 a1 = make_float4(0.f, 0.f, 0.f, 0.f);
        float4 a2 = make_float4(0.f, 0.f, 0.f, 0.f);
        float4 a3 = make_float4(0.f, 0.f, 0.f, 0.f);
        int e0 = g_rowptr[v], e1 = g_rowptr[v + 1];
        int e = e0;
        for (; e + 4 <= e1; e += 4) {
            int2 p0 = g_csr[e + 0];
            int2 p1 = g_csr[e + 1];
            int2 p2 = g_csr[e + 2];
            int2 p3 = g_csr[e + 3];
            float4 h0 = *((const float4*)(g_h + (size_t)p0.x * DD) + lane);
            float4 h1 = *((const float4*)(g_h + (size_t)p1.x * DD) + lane);
            float4 h2 = *((const float4*)(g_h + (size_t)p2.x * DD) + lane);
            float4 h3 = *((const float4*)(g_h + (size_t)p3.x * DD) + lane);
            float c0 = __int_as_float(p0.y), c1 = __int_as_float(p1.y);
            float c2 = __int_as_float(p2.y), c3 = __int_as_float(p3.y);
            a0.x += c0 * h0.x; a0.y += c0 * h0.y; a0.z += c0 * h0.z; a0.w += c0 * h0.w;
            a1.x += c1 * h1.x; a1.y += c1 * h1.y; a1.z += c1 * h1.z; a1.w += c1 * h1.w;
            a2.x += c2 * h2.x; a2.y += c2 * h2.y; a2.z += c2 * h2.z; a2.w += c2 * h2.w;
            a3.x += c3 * h3.x; a3.y += c3 * h3.y; a3.z += c3 * h3.z; a3.w += c3 * h3.w;
        }
        for (; e < e1; e++) {
            int2 p = g_csr[e];
            float c = __int_as_float(p.y);
            float4 hs = *((const float4*)(g_h + (size_t)p.x * DD) + lane);
            a0.x += c * hs.x; a0.y += c * hs.y; a0.z += c * hs.z; a0.w += c * hs.w;
        }
        float4 acc;
        acc.x = (a0.x + a1.x) + (a2.x + a3.x);
        acc.y = (a0.y + a1.y) + (a2.y + a3.y);
        acc.z = (a0.z + a1.z) + (a2.z + a3.z);
        acc.w = (a0.w + a1.w) + (a2.w + a3.w);
        acc.x = fmaxf(acc.x + bb.x, 0.f);
        acc.y = fmaxf(acc.y + bb.y, 0.f);
        acc.z = fmaxf(acc.z + bb.z, 0.f);
        acc.w = fmaxf(acc.w + bb.w, 0.f);
        *((float4*)(g_act + (size_t)v * DD) + lane) = acc;
        s0 += acc.x; s1 += acc.y; s2 += acc.z; s3 += acc.w;
        q0 += acc.x * acc.x; q1 += acc.y * acc.y;
        q2 += acc.z * acc.z; q3 += acc.w * acc.w;
    }
    int c0 = lane * 4;
    atomicAdd(&g_colsum[c0 + 0], s0);
    atomicAdd(&g_colsum[c0 + 1], s1);
    atomicAdd(&g_colsum[c0 + 2], s2);
    atomicAdd(&g_colsum[c0 + 3], s3);
    atomicAdd(&g_colsumsq[c0 + 0], q0);
    atomicAdd(&g_colsumsq[c0 + 1], q1);
    atomicAdd(&g_colsumsq[c0 + 2], q2);
    atomicAdd(&g_colsumsq[c0 + 3], q3);
}

// ---------------- finalize BN affine; re-zero accumulators for next layer ----------------
__global__ void stats_kernel(const float* __restrict__ gam, const float* __restrict__ bet) {
    int c = threadIdx.x;
    float mean = g_colsum[c] * (1.0f / (float)NN);
    float var = g_colsumsq[c] * (1.0f / (float)NN) - mean * mean;
    float rstd = rsqrtf(var + BN_EPS);
    float sc = gam[c] * rstd;
    g_scale[c] = sc;
    g_shift[c] = bet[c] - mean * sc;
    g_colsum[c] = 0.0f;
    g_colsumsq[c] = 0.0f;
    g_cvec[c] = 0.0f;
}

// ---------------- pool ----------------
__global__ void pool_kernel(const int* __restrict__ batch, float* __restrict__ out) {
    int t = threadIdx.x;
    int nb = gridDim.x;
    int per = (NN + nb - 1) / nb;
    int v0 = blockIdx.x * per;
    int v1 = min(NN, v0 + per);
    if (v0 >= v1) return;
    float sc = g_scale[t], sh = g_shift[t];
    float acc = 0.0f;
    int g = batch[v0];
    for (int v = v0; v < v1; v++) {
        int gv = batch[v];
        if (gv != g) {
            atomicAdd(&out[g * DD + t], acc);
            acc = 0.0f;
            g = gv;
        }
        acc += g_act[(size_t)v * DD + t] * sc + sh;
    }
    atomicAdd(&out[g * DD + t], acc);
}

// ---------------- launch ----------------
extern "C" void kernel_launch(void* const* d_in, const int* in_sizes, int n_in,
                              void* d_out, int out_size) {
    const float* x = (const float*)d_in[0];
    const int* ei = (const int*)d_in[1];
    const int* batch = (const int*)d_in[2];
    const float *W[4], *b[4], *gam[4], *bet[4];
    for (int i = 0; i < 4; i++) {
        W[i]   = (const float*)d_in[3 + 4 * i];
        b[i]   = (const float*)d_in[4 + 4 * i];
        gam[i] = (const float*)d_in[5 + 4 * i];
        bet[i] = (const float*)d_in[6 + 4 * i];
    }
    float* out = (float*)d_out;
    float* actp = nullptr;
    cudaGetSymbolAddress((void**)&actp, g_act);

    static bool attr_done = false;
    if (!attr_done) {
        cudaFuncSetAttribute(gemm_kernel,
                             cudaFuncAttributeMaxDynamicSharedMemorySize, GEMM_SMEM);
        attr_done = true;
    }

    init_kernel<<<(NN + 255) / 256, 256>>>(out);          // 1
    fold_kernel<<<64, 256>>>(W[0], b[0]);                 // 2
    count_kernel<<<(EE + 255) / 256, 256>>>(ei);          // 3
    gemm_kernel<<<(NN + 127) / 128, 256, GEMM_SMEM>>>(x); // 4  <-- profiled (control)
    scanA_kernel<<<NB_SCAN, 256>>>();                     // 5 (deg fused)
    scanB_kernel<<<1, 256>>>();                           // 6
    scanC_kernel<<<NB_SCAN, 256>>>();                     // 7
    fill_kernel<<<(EE + 255) / 256, 256>>>(ei);           // 8
    agg_kernel<<<1184, 256>>>();                          // 9
    stats_kernel<<<1, DD>>>(gam[0], bet[0]);              // 10

    for (int L = 1; L < 4; L++) {
        fold_kernel<<<64, 256>>>(W[L], b[L]);
        gemm_kernel<<<(NN + 127) / 128, 256, GEMM_SMEM>>>(actp);
        agg_kernel<<<1184, 256>>>();
        stats_kernel<<<1, DD>>>(gam[L], bet[L]);
    }
    pool_kernel<<<256, DD>>>(batch, out);
}

// round 13
// speedup vs baseline: 1.4457x; 1.4457x over previous
#include <cuda_runtime.h>
#include <cuda_bf16.h>
#include <math.h>

#define NN 50000
#define EE 800000
#define GG 64
#define DD 128
#define BN_EPS 1e-5f
#define NB_SCAN 196   // ceil(50000/256)

#define AS_PAD 36
#define BS_PAD 132
#define GEMM_SMEM ((128 * AS_PAD * 2 + 32 * BS_PAD * 2) * 4)   // 70656 B

// ---------------- scratch (device globals; no allocation) ----------------
__device__ __align__(16) float g_h[NN * DD];
__device__ __align__(16) float g_act[NN * DD];
__device__ __align__(16) int2  g_csr[EE];          // {src, coef bits} packed
__device__ __align__(16) int   g_rowptr[NN + 1];
__device__ __align__(16) int   g_counts[NN];
__device__ __align__(16) int   g_cursor[NN];
__device__ __align__(16) float g_dinv[NN];
__device__ __align__(16) float g_selfw[NN];
__device__ __align__(16) int   g_bsum[NB_SCAN];
__device__ __align__(16) int   g_boff[NB_SCAN];
__device__ __align__(16) float g_Wp[DD * DD];
__device__ __align__(16) float g_cvec[DD];
__device__ __align__(16) float g_bias2[DD];
__device__ __align__(16) float g_colsum[DD];
__device__ __align__(16) float g_colsumsq[DD];
__device__ __align__(16) float g_scale[DD];
__device__ __align__(16) float g_shift[DD];

// ---------------- tf32 helpers ----------------
__device__ __forceinline__ unsigned f2tf32(float x) {
    unsigned r;
    asm("cvt.rna.tf32.f32 %0, %1;" : "=r"(r) : "f"(x));
    return r;
}
__device__ __forceinline__ void mma_tf32(float* d, const unsigned* a, unsigned b0, unsigned b1) {
    asm volatile(
        "mma.sync.aligned.m16n8k8.row.col.f32.tf32.tf32.f32 "
        "{%0,%1,%2,%3}, {%4,%5,%6,%7}, {%8,%9}, {%0,%1,%2,%3};"
        : "+f"(d[0]), "+f"(d[1]), "+f"(d[2]), "+f"(d[3])
        : "r"(a[0]), "r"(a[1]), "r"(a[2]), "r"(a[3]), "r"(b0), "r"(b1));
}
// split a float4 into hi/lo tf32 quads, store as two STS.128
__device__ __forceinline__ void split4_store(float4 v, unsigned* hp, unsigned* lp) {
    unsigned h0 = f2tf32(v.x), h1 = f2tf32(v.y), h2 = f2tf32(v.z), h3 = f2tf32(v.w);
    unsigned l0 = f2tf32(v.x - __uint_as_float(h0));
    unsigned l1 = f2tf32(v.y - __uint_as_float(h1));
    unsigned l2 = f2tf32(v.z - __uint_as_float(h2));
    unsigned l3 = f2tf32(v.w - __uint_as_float(h3));
    *(uint4*)hp = make_uint4(h0, h1, h2, h3);
    *(uint4*)lp = make_uint4(l0, l1, l2, l3);
}

// ---------------- init ----------------
__global__ void init_kernel(float* out) {
    int i = blockIdx.x * blockDim.x + threadIdx.x;
    if (i < NN) g_counts[i] = 0;
    if (i < DD) {
        g_scale[i] = 1.0f; g_shift[i] = 0.0f;
        g_cvec[i] = 0.0f; g_colsum[i] = 0.0f; g_colsumsq[i] = 0.0f;
    }
    if (i < GG * DD) out[i] = 0.0f;
}

// ---------------- degree count (in-degree of dst) ----------------
__global__ void count_kernel(const int* __restrict__ ei) {
    int e = blockIdx.x * blockDim.x + threadIdx.x;
    if (e >= EE) return;
    atomicAdd(&g_counts[ei[EE + e]], 1);
}

// ---------------- scan phase A (fused with deg) ----------------
__device__ __forceinline__ int block_incl_scan_256(int v, int* ws) {
    int lane = threadIdx.x & 31, wid = threadIdx.x >> 5;
    int x = v;
    #pragma unroll
    for (int off = 1; off < 32; off <<= 1) {
        int t = __shfl_up_sync(0xFFFFFFFFu, x, off);
        if (lane >= off) x += t;
    }
    if (lane == 31) ws[wid] = x;
    __syncthreads();
    if (threadIdx.x < 8) {
        int y = ws[threadIdx.x];
        #pragma unroll
        for (int off = 1; off < 8; off <<= 1) {
            int t = __shfl_up_sync(0xFFu, y, off);
            if ((int)threadIdx.x >= off) y += t;
        }
        ws[threadIdx.x] = y;
    }
    __syncthreads();
    return x + ((wid > 0) ? ws[wid - 1] : 0);
}

__global__ void scanA_kernel() {
    __shared__ int ws[8];
    int i = blockIdx.x * 256 + threadIdx.x;
    int v = (i < NN) ? g_counts[i] : 0;
    if (i < NN) {
        float deg = 1.0f + (float)v;
        g_dinv[i] = rsqrtf(deg);
        g_selfw[i] = 1.0f / deg;
    }
    int incl = block_incl_scan_256(v, ws);
    if (i < NN) {
        g_rowptr[i + 1] = incl;
        g_cursor[i] = incl - v;
    }
    if (threadIdx.x == 255) g_bsum[blockIdx.x] = incl;
}

__global__ void scanB_kernel() {
    __shared__ int ws[8];
    int b = threadIdx.x;
    int v = (b < NB_SCAN) ? g_bsum[b] : 0;
    int incl = block_incl_scan_256(v, ws);
    if (b < NB_SCAN) g_boff[b] = incl - v;
    if (b == 0) g_rowptr[0] = 0;
}

__global__ void scanC_kernel() {
    int i = blockIdx.x * 256 + threadIdx.x;
    if (i >= NN) return;
    int off = g_boff[blockIdx.x];
    g_rowptr[i + 1] += off;
    g_cursor[i] += off;
}

// ---------------- CSR fill (packed records) ----------------
__global__ void fill_kernel(const int* __restrict__ ei) {
    int e = blockIdx.x * blockDim.x + threadIdx.x;
    if (e >= EE) return;
    int s = ei[e];
    int d = ei[EE + e];
    float c = g_dinv[s] * g_dinv[d];
    int slot = atomicAdd(&g_cursor[d], 1);
    g_csr[slot] = make_int2(s, __float_as_int(c));
}

// ---------------- fold ----------------
__global__ void fold_kernel(const float* __restrict__ W, const float* __restrict__ b) {
    int idx = blockIdx.x * blockDim.x + threadIdx.x;   // 0..16383
    int k = idx >> 7;
    int n = idx & 127;
    float w = W[idx];
    g_Wp[idx] = g_scale[k] * w;
    float contrib = g_shift[k] * w;
    if (contrib != 0.0f) atomicAdd(&g_cvec[n], contrib);
    if (idx < DD) g_bias2[idx] = b[idx];
}

// ---------------- GEMM: g_h = X @ g_Wp + cvec  (tf32 mma, 2-term split) ----------------
__global__ void __launch_bounds__(256, 2) gemm_kernel(const float* __restrict__ X) {
    extern __shared__ unsigned smem[];
    unsigned* AsH = smem;
    unsigned* AsL = AsH + 128 * AS_PAD;
    unsigned* BsH = AsL + 128 * AS_PAD;
    unsigned* BsL = BsH + 32 * BS_PAD;

    int tid = threadIdx.x;
    int lane = tid & 31, warp = tid >> 5;
    int wm = warp >> 1, wn = warp & 1;
    int g = lane >> 2, tig = lane & 3;
    int m0 = blockIdx.x * 128;

    float c[2][8][4];
    #pragma unroll
    for (int mt = 0; mt < 2; mt++)
        #pragma unroll
        for (int nt = 0; nt < 8; nt++)
            #pragma unroll
            for (int q = 0; q < 4; q++) c[mt][nt][q] = 0.0f;

    int lm  = tid >> 1;
    int lk0 = (tid & 1) * 16;
    int lkb = tid >> 3;
    int ln0 = (tid & 7) * 16;
    bool valid = (m0 + lm) < NN;

    for (int chunk = 0; chunk < 4; chunk++) {
        int kk = chunk * 32;
        const float* xr = X + (size_t)(m0 + lm) * DD + kk + lk0;
        #pragma unroll
        for (int j = 0; j < 16; j += 4) {
            float4 v = valid ? *(const float4*)(xr + j) : make_float4(0.f, 0.f, 0.f, 0.f);
            int base = lm * AS_PAD + lk0 + j;      // div by 4 -> 16B aligned
            split4_store(v, &AsH[base], &AsL[base]);
        }
        const float* wr = g_Wp + (size_t)(kk + lkb) * DD + ln0;
        #pragma unroll
        for (int j = 0; j < 16; j += 4) {
            float4 v = *(const float4*)(wr + j);
            int base = lkb * BS_PAD + ln0 + j;     // div by 4 -> 16B aligned
            split4_store(v, &BsH[base], &BsL[base]);
        }
        __syncthreads();

        #pragma unroll
        for (int ks = 0; ks < 4; ks++) {
            int kb = ks * 8;
            unsigned aH[2][4], aL[2][4];
            #pragma unroll
            for (int mt = 0; mt < 2; mt++) {
                int r0 = (wm * 32 + mt * 16 + g) * AS_PAD;
                int r8 = r0 + 8 * AS_PAD;
                aH[mt][0] = AsH[r0 + kb + tig];
                aH[mt][1] = AsH[r8 + kb + tig];
                aH[mt][2] = AsH[r0 + kb + tig + 4];
                aH[mt][3] = AsH[r8 + kb + tig + 4];
                aL[mt][0] = AsL[r0 + kb + tig];
                aL[mt][1] = AsL[r8 + kb + tig];
                aL[mt][2] = AsL[r0 + kb + tig + 4];
                aL[mt][3] = AsL[r8 + kb + tig + 4];
            }
            #pragma unroll
            for (int nt = 0; nt < 8; nt++) {
                int ncol = wn * 64 + nt * 8 + g;
                int kr = (kb + tig) * BS_PAD + ncol;
                unsigned bH0 = BsH[kr];
                unsigned bH1 = BsH[kr + 4 * BS_PAD];
                unsigned bL0 = BsL[kr];
                unsigned bL1 = BsL[kr + 4 * BS_PAD];
                #pragma unroll
                for (int mt = 0; mt < 2; mt++) {
                    mma_tf32(c[mt][nt], aH[mt], bH0, bH1);
                    mma_tf32(c[mt][nt], aH[mt], bL0, bL1);
                    mma_tf32(c[mt][nt], aL[mt], bH0, bH1);
                }
            }
        }
        __syncthreads();
    }

    #pragma unroll
    for (int mt = 0; mt < 2; mt++) {
        int r0 = m0 + wm * 32 + mt * 16 + g;
        int r1 = r0 + 8;
        #pragma unroll
        for (int nt = 0; nt < 8; nt++) {
            int col = wn * 64 + nt * 8 + tig * 2;
            float2 cv = *(const float2*)(g_cvec + col);
            if (r0 < NN) {
                float2 o = make_float2(c[mt][nt][0] + cv.x, c[mt][nt][1] + cv.y);
                *(float2*)(g_h + (size_t)r0 * DD + col) = o;
            }
            if (r1 < NN) {
                float2 o = make_float2(c[mt][nt][2] + cv.x, c[mt][nt][3] + cv.y);
                *(float2*)(g_h + (size_t)r1 * DD + col) = o;
            }
        }
    }
}

// ---------------- aggregate + bias + relu + BN-stat accumulation ----------------
__global__ void agg_kernel() {
    int gtid = blockIdx.x * blockDim.x + threadIdx.x;
    int warp = gtid >> 5;
    int lane = threadIdx.x & 31;
    int nwarps = (gridDim.x * blockDim.x) >> 5;

    float4 bb = *(const float4*)(g_bias2 + lane * 4);
    float s0 = 0.f, s1 = 0.f, s2 = 0.f, s3 = 0.f;
    float q0 = 0.f, q1 = 0.f, q2 = 0.f, q3 = 0.f;

    for (int v = warp; v < NN; v += nwarps) {
        const float4* hv = (const float4*)(g_h + (size_t)v * DD) + lane;
        float4 h = *hv;
        float sw = g_selfw[v];
        float4 a0 = make_float4(h.x * sw, h.y * sw, h.z * sw, h.w * sw);
        float4 a1 = make_float4(0.f, 0.f, 0.f, 0.f);
        float4 a2 = make_float4(0.f, 0.f, 0.f, 0.f);
        float4 a3 = make_float4(0.f, 0.f, 0.f, 0.f);
        int e0 = g_rowptr[v], e1 = g_rowptr[v + 1];
        int e = e0;
        for (; e + 4 <= e1; e += 4) {
            int2 p0 = g_csr[e + 0];
            int2 p1 = g_csr[e + 1];
            int2 p2 = g_csr[e + 2];
            int2 p3 = g_csr[e + 3];
            float4 h0 = *((const float4*)(g_h + (size_t)p0.x * DD) + lane);
            float4 h1 = *((const float4*)(g_h + (size_t)p1.x * DD) + lane);
            float4 h2 = *((const float4*)(g_h + (size_t)p2.x * DD) + lane);
            float4 h3 = *((const float4*)(g_h + (size_t)p3.x * DD) + lane);
            float c0 = __int_as_float(p0.y), c1 = __int_as_float(p1.y);
            float c2 = __int_as_float(p2.y), c3 = __int_as_float(p3.y);
            a0.x += c0 * h0.x; a0.y += c0 * h0.y; a0.z += c0 * h0.z; a0.w += c0 * h0.w;
            a1.x += c1 * h1.x; a1.y += c1 * h1.y; a1.z += c1 * h1.z; a1.w += c1 * h1.w;
            a2.x += c2 * h2.x; a2.y += c2 * h2.y; a2.z += c2 * h2.z; a2.w += c2 * h2.w;
            a3.x += c3 * h3.x; a3.y += c3 * h3.y; a3.z += c3 * h3.z; a3.w += c3 * h3.w;
        }
        for (; e < e1; e++) {
            int2 p = g_csr[e];
            float c = __int_as_float(p.y);
            float4 hs = *((const float4*)(g_h + (size_t)p.x * DD) + lane);
            a0.x += c * hs.x; a0.y += c * hs.y; a0.z += c * hs.z; a0.w += c * hs.w;
        }
        float4 acc;
        acc.x = (a0.x + a1.x) + (a2.x + a3.x);
        acc.y = (a0.y + a1.y) + (a2.y + a3.y);
        acc.z = (a0.z + a1.z) + (a2.z + a3.z);
        acc.w = (a0.w + a1.w) + (a2.w + a3.w);
        acc.x = fmaxf(acc.x + bb.x, 0.f);
        acc.y = fmaxf(acc.y + bb.y, 0.f);
        acc.z = fmaxf(acc.z + bb.z, 0.f);
        acc.w = fmaxf(acc.w + bb.w, 0.f);
        *((float4*)(g_act + (size_t)v * DD) + lane) = acc;
        s0 += acc.x; s1 += acc.y; s2 += acc.z; s3 += acc.w;
        q0 += acc.x * acc.x; q1 += acc.y * acc.y;
        q2 += acc.z * acc.z; q3 += acc.w * acc.w;
    }
    int c0 = lane * 4;
    atomicAdd(&g_colsum[c0 + 0], s0);
    atomicAdd(&g_colsum[c0 + 1], s1);
    atomicAdd(&g_colsum[c0 + 2], s2);
    atomicAdd(&g_colsum[c0 + 3], s3);
    atomicAdd(&g_colsumsq[c0 + 0], q0);
    atomicAdd(&g_colsumsq[c0 + 1], q1);
    atomicAdd(&g_colsumsq[c0 + 2], q2);
    atomicAdd(&g_colsumsq[c0 + 3], q3);
}

// ---------------- finalize BN affine; re-zero accumulators ----------------
__global__ void stats_kernel(const float* __restrict__ gam, const float* __restrict__ bet) {
    int c = threadIdx.x;
    float mean = g_colsum[c] * (1.0f / (float)NN);
    float var = g_colsumsq[c] * (1.0f / (float)NN) - mean * mean;
    float rstd = rsqrtf(var + BN_EPS);
    float sc = gam[c] * rstd;
    g_scale[c] = sc;
    g_shift[c] = bet[c] - mean * sc;
    g_colsum[c] = 0.0f;
    g_colsumsq[c] = 0.0f;
    g_cvec[c] = 0.0f;
}

// ---------------- pool ----------------
__global__ void pool_kernel(const int* __restrict__ batch, float* __restrict__ out) {
    int t = threadIdx.x;
    int nb = gridDim.x;
    int per = (NN + nb - 1) / nb;
    int v0 = blockIdx.x * per;
    int v1 = min(NN, v0 + per);
    if (v0 >= v1) return;
    float sc = g_scale[t], sh = g_shift[t];
    float acc = 0.0f;
    int g = batch[v0];
    for (int v = v0; v < v1; v++) {
        int gv = batch[v];
        if (gv != g) {
            atomicAdd(&out[g * DD + t], acc);
            acc = 0.0f;
            g = gv;
        }
        acc += g_act[(size_t)v * DD + t] * sc + sh;
    }
    atomicAdd(&out[g * DD + t], acc);
}

// ---------------- launch ----------------
extern "C" void kernel_launch(void* const* d_in, const int* in_sizes, int n_in,
                              void* d_out, int out_size) {
    const float* x = (const float*)d_in[0];
    const int* ei = (const int*)d_in[1];
    const int* batch = (const int*)d_in[2];
    const float *W[4], *b[4], *gam[4], *bet[4];
    for (int i = 0; i < 4; i++) {
        W[i]   = (const float*)d_in[3 + 4 * i];
        b[i]   = (const float*)d_in[4 + 4 * i];
        gam[i] = (const float*)d_in[5 + 4 * i];
        bet[i] = (const float*)d_in[6 + 4 * i];
    }
    float* out = (float*)d_out;
    float* actp = nullptr;
    cudaGetSymbolAddress((void**)&actp, g_act);

    static bool attr_done = false;
    if (!attr_done) {
        cudaFuncSetAttribute(gemm_kernel,
                             cudaFuncAttributeMaxDynamicSharedMemorySize, GEMM_SMEM);
        attr_done = true;
    }

    init_kernel<<<(NN + 255) / 256, 256>>>(out);          // 1
    fold_kernel<<<64, 256>>>(W[0], b[0]);                 // 2
    count_kernel<<<(EE + 255) / 256, 256>>>(ei);          // 3
    gemm_kernel<<<(NN + 127) / 128, 256, GEMM_SMEM>>>(x); // 4  <-- profiled
    scanA_kernel<<<NB_SCAN, 256>>>();                     // 5 (deg fused)
    scanB_kernel<<<1, 256>>>();                           // 6
    scanC_kernel<<<NB_SCAN, 256>>>();                     // 7
    fill_kernel<<<(EE + 255) / 256, 256>>>(ei);           // 8
    agg_kernel<<<592, 256>>>();                           // 9  (grid reverted: 1184 was a regression)
    stats_kernel<<<1, DD>>>(gam[0], bet[0]);              // 10

    for (int L = 1; L < 4; L++) {
        fold_kernel<<<64, 256>>>(W[L], b[L]);
        gemm_kernel<<<(NN + 127) / 128, 256, GEMM_SMEM>>>(actp);
        agg_kernel<<<592, 256>>>();
        stats_kernel<<<1, DD>>>(gam[L], bet[L]);
    }
    pool_kernel<<<256, DD>>>(batch, out);
}